// round 7
// baseline (speedup 1.0000x reference)
#include <cuda_runtime.h>
#include <math.h>

#define WRANKS 4
#define NUM_HEADS 32
#define HEAD_SIZE 128
#define GKV 8              // kv heads
#define QPG 4              // query heads per kv head
#define BLOCK_SIZE 16
#define NUM_BLOCKS 1024
#define MAX_BLOCKS 32
#define MAX_CTX 512
#define NSEQ 32
#define NCHUNK 4
#define CHUNK 128
#define NPER (WRANKS * NCHUNK)                 // 16 partials per (seq, g)
#define NPART (NSEQ * GKV * NPER)              // 4096 partials
#define ATT_SCALE 0.08838834764831845f         // 1/sqrt(128)

// Partial-result scratch — __device__ globals (zero-initialized at load).
__device__ float g_num[NPART][QPG][HEAD_SIZE]; // 8 MB
__device__ float g_m[NPART][QPG];
__device__ float g_e[NPART][QPG];
__device__ int   g_cnt[NSEQ * GKV];            // arrival counters (reset by last CTA)

__device__ __forceinline__ int pidx(int w, int s, int g, int c) {
    return ((w * NSEQ + s) * GKV + g) * NCHUNK + c;
}

// Merge two butterfly-reduction streams: lanes where cond!=0 track y's series,
// others track x's. One SHFL per merge instead of one per value per level.
__device__ __forceinline__ float mergestep(float x, float y, int cond, int d) {
    const float keep = cond ? y : x;
    const float send = cond ? x : y;
    return keep + __shfl_xor_sync(0xFFFFFFFFu, send, d);
}

// ---------------------------------------------------------------------------
// Fused kernel: partial attention + last-block cross-partial LSE merge.
// grid = (NSEQ*GKV, WRANKS, NCHUNK), block = 256
// ---------------------------------------------------------------------------
__global__ __launch_bounds__(256, 3)
void dpa_fused(const float* __restrict__ query,
               const float* __restrict__ key_cache,
               const float* __restrict__ value_cache,
               const int*   __restrict__ block_tables,
               const int*   __restrict__ context_lens,
               float*       __restrict__ out)
{
    __shared__ float smem[4096];             // 16 KB: logits (2KB) / red [8][4][128] / reduce m-e
    __shared__ int   bt_s[MAX_BLOCKS];
    __shared__ float m_s[QPG], e_s[QPG];
    __shared__ int   is_last_s;

    const int sg   = blockIdx.x;             // 0..255
    const int s    = sg >> 3;
    const int g    = sg & 7;
    const int w    = blockIdx.y;
    const int c    = blockIdx.z;
    const int tid  = threadIdx.x;
    const int lane = tid & 31;
    const int warp = tid >> 5;

    const int P = pidx(w, s, g, c);

    const int ctx = context_lens[w * NSEQ + s];
    const int t0  = c * CHUNK;
    const int t1  = min(ctx, t0 + CHUNK);
    const int n   = t1 - t0;

    if (n > 0) {
        if (tid < MAX_BLOCKS)
            bt_s[tid] = block_tables[((size_t)w * NSEQ + s) * MAX_BLOCKS + tid];

        // Q fragments, pre-scaled
        float4 qf[QPG];
        const float* qb = query + (size_t)s * (NUM_HEADS * HEAD_SIZE)
                                + (size_t)g * (QPG * HEAD_SIZE) + lane * 4;
        #pragma unroll
        for (int h = 0; h < QPG; h++) {
            float4 q4 = *(const float4*)(qb + h * HEAD_SIZE);
            q4.x *= ATT_SCALE; q4.y *= ATT_SCALE; q4.z *= ATT_SCALE; q4.w *= ATT_SCALE;
            qf[h] = q4;
        }
        __syncthreads();

        float* logits = smem;  // [QPG][CHUNK]

        const size_t rank_stride = (size_t)NUM_BLOCKS * GKV * BLOCK_SIZE * HEAD_SIZE;
        const size_t page_stride = (size_t)GKV * BLOCK_SIZE * HEAD_SIZE;

        // ---- QK: 4 tokens in flight per warp-iter (32-token span) ----------
        // tokens: base+warp+8j, j=0..3.  j<2 -> page base>>4, j>=2 -> page+1.
        const float* kc = key_cache + (size_t)w * rank_stride
                        + (size_t)g * (BLOCK_SIZE * HEAD_SIZE);
        const int cb0 = lane & 1, cb1 = lane & 2, cb2 = lane & 4, cb3 = lane & 8;
        for (int base = t0; base < t1; base += 32) {
            const size_t kb0 = (size_t)bt_s[base >> 4] * page_stride;
            const size_t kb1 = (size_t)bt_s[(base >> 4) + 1] * page_stride;
            int   tok[4];
            float4 k4[4];
            #pragma unroll
            for (int j = 0; j < 4; j++) {
                tok[j] = base + warp + 8 * j;
                k4[j] = make_float4(0.f, 0.f, 0.f, 0.f);
            }
            if (tok[0] < t1)
                k4[0] = *(const float4*)(kc + kb0 + (size_t)warp * HEAD_SIZE + lane * 4);
            if (tok[1] < t1)
                k4[1] = *(const float4*)(kc + kb0 + (size_t)(warp + 8) * HEAD_SIZE + lane * 4);
            if (tok[2] < t1)
                k4[2] = *(const float4*)(kc + kb1 + (size_t)warp * HEAD_SIZE + lane * 4);
            if (tok[3] < t1)
                k4[3] = *(const float4*)(kc + kb1 + (size_t)(warp + 8) * HEAD_SIZE + lane * 4);

            float p[4][QPG];
            #pragma unroll
            for (int j = 0; j < 4; j++) {
                #pragma unroll
                for (int h = 0; h < QPG; h++) {
                    float x = k4[j].x * qf[h].x;
                    x = fmaf(k4[j].y, qf[h].y, x);
                    x = fmaf(k4[j].z, qf[h].z, x);
                    x = fmaf(k4[j].w, qf[h].w, x);
                    p[j][h] = x;
                }
            }
            // merged reduction of 16 series: head = lane bits 0-1, token j = bits 2-3
            float r[4];
            #pragma unroll
            for (int j = 0; j < 4; j++) {
                const float a = mergestep(p[j][0], p[j][1], cb0, 1);
                const float b = mergestep(p[j][2], p[j][3], cb0, 1);
                r[j] = mergestep(a, b, cb1, 2);
            }
            const float s0 = mergestep(r[0], r[1], cb2, 4);
            const float s1 = mergestep(r[2], r[3], cb2, 4);
            float t = mergestep(s0, s1, cb3, 8);
            t += __shfl_xor_sync(0xFFFFFFFFu, t, 16);
            // lane < 16 holds (head = lane&3, token = base+warp+8*((lane>>2)&3))
            if (lane < 16) {
                const int tj = base + warp + 8 * (lane >> 2);
                if (tj < t1)
                    logits[(lane & 3) * CHUNK + (tj - t0)] = t;
            }
        }
        __syncthreads();

        // ---- per-head softmax, p in-place ------------------------------
        if (warp < QPG) {
            const int h = warp;
            float mx = -1e30f;
            for (int t = lane; t < n; t += 32)
                mx = fmaxf(mx, logits[h * CHUNK + t]);
            #pragma unroll
            for (int off = 16; off; off >>= 1)
                mx = fmaxf(mx, __shfl_xor_sync(0xFFFFFFFFu, mx, off));
            float sum = 0.0f;
            for (int t = lane; t < n; t += 32) {
                const float p = __expf(logits[h * CHUNK + t] - mx);
                logits[h * CHUNK + t] = p;
                sum += p;
            }
            #pragma unroll
            for (int off = 16; off; off >>= 1)
                sum += __shfl_xor_sync(0xFFFFFFFFu, sum, off);
            if (lane == 0) { m_s[h] = mx; e_s[h] = sum; }
        }
        __syncthreads();

        // ---- PV: 4 independent V LDG.128 per 32-token span ------------
        const float* vc = value_cache + (size_t)w * rank_stride
                        + (size_t)g * (BLOCK_SIZE * HEAD_SIZE) + lane * 4;
        float4 pv[QPG];
        #pragma unroll
        for (int h = 0; h < QPG; h++)
            pv[h] = make_float4(0.f, 0.f, 0.f, 0.f);

        for (int base = t0; base < t1; base += 32) {
            const size_t vb0 = (size_t)bt_s[base >> 4] * page_stride;
            const size_t vb1 = (size_t)bt_s[(base >> 4) + 1] * page_stride;
            int tok[4];
            float4 v4[4];
            #pragma unroll
            for (int j = 0; j < 4; j++) tok[j] = base + warp + 8 * j;
            if (tok[0] < t1) v4[0] = *(const float4*)(vc + vb0 + (size_t)warp * HEAD_SIZE);
            if (tok[1] < t1) v4[1] = *(const float4*)(vc + vb0 + (size_t)(warp + 8) * HEAD_SIZE);
            if (tok[2] < t1) v4[2] = *(const float4*)(vc + vb1 + (size_t)warp * HEAD_SIZE);
            if (tok[3] < t1) v4[3] = *(const float4*)(vc + vb1 + (size_t)(warp + 8) * HEAD_SIZE);
            #pragma unroll
            for (int j = 0; j < 4; j++) {
                if (tok[j] < t1) {
                    #pragma unroll
                    for (int h = 0; h < QPG; h++) {
                        const float p = logits[h * CHUNK + (tok[j] - t0)];
                        pv[h].x = fmaf(p, v4[j].x, pv[h].x);
                        pv[h].y = fmaf(p, v4[j].y, pv[h].y);
                        pv[h].z = fmaf(p, v4[j].z, pv[h].z);
                        pv[h].w = fmaf(p, v4[j].w, pv[h].w);
                    }
                }
            }
        }

        // ---- cross-warp (8-way) reduction, write partials ---------------
        __syncthreads();
        float4* red = (float4*)smem;   // [8 warps][QPG][32 float4s]
        #pragma unroll
        for (int h = 0; h < QPG; h++)
            red[(warp * QPG + h) * 32 + lane] = pv[h];
        __syncthreads();

        #pragma unroll
        for (int it = 0; it < 2; it++) {
            const int idx = tid + it * 256;     // 0..511 = (h, d)
            const int h = idx >> 7, d = idx & 127;
            float v = 0.0f;
            #pragma unroll
            for (int e = 0; e < 8; e++)
                v += smem[(e * QPG + h) * 128 + d];
            g_num[P][h][d] = v;
        }
        if (tid < QPG) { g_m[P][tid] = m_s[tid]; g_e[P][tid] = e_s[tid]; }
    } else {
        // Empty partial: weight will be exactly 0; skip num writes entirely.
        if (tid < QPG) { g_m[P][tid] = -1e30f; g_e[P][tid] = 0.0f; }
    }

    // ---- last-block arrival + fused reduce ---------------------------------
    __syncthreads();                 // all global writes of this CTA issued
    if (tid == 0) {
        __threadfence();             // release
        is_last_s = (atomicAdd(&g_cnt[sg], 1) == NPER - 1);
    }
    __syncthreads();
    if (!is_last_s) return;

    __threadfence();                 // acquire

    float* sm = smem;                // [NPER][QPG]
    float* se = smem + NPER * QPG;
    if (tid < NPER * QPG) {
        const int p = tid >> 2, h = tid & 3;
        const int Pq = pidx(p >> 2, s, g, p & 3);   // p = w*4 + c
        sm[tid] = g_m[Pq][h];
        se[p * QPG + h] = g_e[Pq][h];
    }
    __syncthreads();

    #pragma unroll
    for (int it = 0; it < 2; it++) {
        const int idx = tid + it * 256;     // (h, d)
        const int h = idx >> 7, d = idx & 127;
        float gmax = -1e30f;
        #pragma unroll
        for (int p = 0; p < NPER; p++)
            gmax = fmaxf(gmax, sm[p * QPG + h]);
        float den = 0.0f, val = 0.0f;
        #pragma unroll
        for (int p = 0; p < NPER; p++) {
            const float wgt = __expf(sm[p * QPG + h] - gmax);
            const int Pq = pidx(p >> 2, s, g, p & 3);
            den = fmaf(se[p * QPG + h], wgt, den);
            val = fmaf(g_num[Pq][h][d], wgt, val);
        }
        out[(size_t)sg * (QPG * HEAD_SIZE) + h * HEAD_SIZE + d] = val / den;
    }

    if (tid == 0) g_cnt[sg] = 0;
}

extern "C" void kernel_launch(void* const* d_in, const int* in_sizes, int n_in,
                              void* d_out, int out_size)
{
    const float* query        = (const float*)d_in[0];
    const float* key_cache    = (const float*)d_in[1];
    const float* value_cache  = (const float*)d_in[2];
    const int*   block_tables = (const int*)d_in[3];
    const int*   context_lens = (const int*)d_in[4];
    float*       out          = (float*)d_out;

    dim3 grid(NSEQ * GKV, WRANKS, NCHUNK);
    dpa_fused<<<grid, 256>>>(query, key_cache, value_cache,
                             block_tables, context_lens, out);
}

// round 8
// speedup vs baseline: 1.0206x; 1.0206x over previous
#include <cuda_runtime.h>
#include <stdint.h>
#include <math.h>

#define WRANKS 4
#define NUM_HEADS 32
#define HEAD_SIZE 128
#define GKV 8              // kv heads
#define QPG 4              // query heads per kv head
#define BLOCK_SIZE 16
#define NUM_BLOCKS 1024
#define MAX_BLOCKS 32
#define MAX_CTX 512
#define NSEQ 32
#define NCHUNK 4
#define CHUNK 128
#define NPER (WRANKS * NCHUNK)                 // 16 partials per (seq, g)
#define NPART (NSEQ * GKV * NPER)              // 4096 partials
#define ATT_SCALE 0.08838834764831845f         // 1/sqrt(128)

#define PAGE_BYTES 65536                       // GKV*BLOCK_SIZE*HEAD_SIZE*4
#define RANK_BYTES ((size_t)NUM_BLOCKS * PAGE_BYTES)
#define GOFF_BYTES (BLOCK_SIZE * HEAD_SIZE * 4)  // 8192

// Partial-result scratch — __device__ globals.
__device__ float g_num[NPART][QPG][HEAD_SIZE]; // 8 MB
__device__ float g_m[NPART][QPG];
__device__ float g_e[NPART][QPG];
__device__ int   g_cnt[NSEQ * GKV];            // arrival counters (reset by last CTA)

__device__ __forceinline__ int pidx(int w, int s, int g, int c) {
    return ((w * NSEQ + s) * GKV + g) * NCHUNK + c;
}

// Merge two butterfly-reduction streams (1 SHFL per merge).
__device__ __forceinline__ float mergestep(float x, float y, int cond, int d) {
    const float keep = cond ? y : x;
    const float send = cond ? x : y;
    return keep + __shfl_xor_sync(0xFFFFFFFFu, send, d);
}

__device__ __forceinline__ uint64_t pack2(float p) {
    const uint32_t u = __float_as_uint(p);
    uint64_t r;
    asm("mov.b64 %0, {%1, %2};" : "=l"(r) : "r"(u), "r"(u));
    return r;
}
__device__ __forceinline__ void ffma2(uint64_t& acc, uint64_t a, uint64_t b) {
    asm("fma.rn.f32x2 %0, %1, %2, %0;" : "+l"(acc) : "l"(a), "l"(b));
}
__device__ __forceinline__ float2 unpack2(uint64_t v) {
    uint32_t lo, hi;
    asm("mov.b64 {%0, %1}, %2;" : "=r"(lo), "=r"(hi) : "l"(v));
    return make_float2(__uint_as_float(lo), __uint_as_float(hi));
}

// ---------------------------------------------------------------------------
// Fused kernel: partial attention + last-block cross-partial LSE merge.
// grid = (NSEQ*GKV, WRANKS, NCHUNK), block = 256
// ---------------------------------------------------------------------------
__global__ __launch_bounds__(256, 5)
void dpa_fused(const float* __restrict__ query,
               const float* __restrict__ key_cache,
               const float* __restrict__ value_cache,
               const int*   __restrict__ block_tables,
               const int*   __restrict__ context_lens,
               float*       __restrict__ out)
{
    __shared__ float smem[4096];          // 16 KB: logits[512] + qs[512]; later red[4096]
    __shared__ int   bt_s[8];             // only this chunk's 8 pages
    __shared__ float m_s[QPG], e_s[QPG];
    __shared__ int   is_last_s;

    const int sg   = blockIdx.x;          // 0..255
    const int s    = sg >> 3;
    const int g    = sg & 7;
    const int w    = blockIdx.y;
    const int c    = blockIdx.z;
    const int tid  = threadIdx.x;
    const int lane = tid & 31;
    const int warp = tid >> 5;

    const int P   = pidx(w, s, g, c);
    const int ctx = context_lens[w * NSEQ + s];
    const int t0  = c * CHUNK;
    const int n   = min(ctx - t0, CHUNK);   // may be <=0

    if (n > 0) {
        if (tid < 8)
            bt_s[tid] = block_tables[((size_t)w * NSEQ + s) * MAX_BLOCKS + c * 8 + tid];

        float* logits = smem;         // [CHUNK][QPG] transposed, 512 floats
        float* qs     = smem + 512;   // [QPG][HEAD_SIZE], pre-scaled

        for (int i = tid; i < QPG * HEAD_SIZE; i += 256)
            qs[i] = query[(size_t)s * (NUM_HEADS * HEAD_SIZE)
                          + (size_t)g * (QPG * HEAD_SIZE) + i] * ATT_SCALE;
        __syncthreads();

        const char* kwp = (const char*)key_cache + (size_t)w * RANK_BYTES
                        + g * GOFF_BYTES + warp * 512 + lane * 16;
        const char* vwp = (const char*)value_cache + (size_t)w * RANK_BYTES
                        + g * GOFF_BYTES + warp * 512 + lane * 16;
        const float* qlp = qs + lane * 4;
        const int cb0 = lane & 1, cb1 = lane & 2, cb2 = lane & 4;

        // ---- QK: all 8 pages, no token guards (garbage logits zeroed later)
        #pragma unroll 2
        for (int base = 0; base < CHUNK; base += 16) {
            const uint32_t po = ((uint32_t)bt_s[base >> 4]) << 16;
            const float4 ka = *(const float4*)(kwp + po);
            const float4 kb = *(const float4*)(kwp + po + 4096);
            float pa[QPG], pb[QPG];
            #pragma unroll
            for (int h = 0; h < QPG; h++) {
                const float4 q4 = *(const float4*)(qlp + h * HEAD_SIZE);
                float x = ka.x * q4.x;
                x = fmaf(ka.y, q4.y, x);
                x = fmaf(ka.z, q4.z, x);
                x = fmaf(ka.w, q4.w, x);
                pa[h] = x;
                float y = kb.x * q4.x;
                y = fmaf(kb.y, q4.y, y);
                y = fmaf(kb.z, q4.z, y);
                y = fmaf(kb.w, q4.w, y);
                pb[h] = y;
            }
            const float r01 = mergestep(pa[0], pa[1], cb0, 1);
            const float r23 = mergestep(pa[2], pa[3], cb0, 1);
            const float s01 = mergestep(pb[0], pb[1], cb0, 1);
            const float s23 = mergestep(pb[2], pb[3], cb0, 1);
            const float r   = mergestep(r01, r23, cb1, 2);
            const float sB  = mergestep(s01, s23, cb1, 2);
            float t = mergestep(r, sB, cb2, 4);
            t += __shfl_xor_sync(0xFFFFFFFFu, t, 8);
            t += __shfl_xor_sync(0xFFFFFFFFu, t, 16);
            if (lane < 8) {
                const int tok = base + warp + ((lane >> 2) << 3);
                logits[tok * QPG + (lane & 3)] = t;
            }
        }
        __syncthreads();

        // ---- softmax (warps 0-3), zero-fill of tail (warps 4-7) ------------
        if (warp < QPG) {
            const int h = warp;
            float mx = -1e30f;
            for (int t = lane; t < n; t += 32)
                mx = fmaxf(mx, logits[t * QPG + h]);
            #pragma unroll
            for (int off = 16; off; off >>= 1)
                mx = fmaxf(mx, __shfl_xor_sync(0xFFFFFFFFu, mx, off));
            float sum = 0.0f;
            for (int t = lane; t < n; t += 32) {
                const float p = __expf(logits[t * QPG + h] - mx);
                logits[t * QPG + h] = p;
                sum += p;
            }
            #pragma unroll
            for (int off = 16; off; off >>= 1)
                sum += __shfl_xor_sync(0xFFFFFFFFu, sum, off);
            if (lane == 0) { m_s[h] = mx; e_s[h] = sum; }
        } else {
            for (int i = n * QPG + (tid - 128); i < CHUNK * QPG; i += 128)
                logits[i] = 0.0f;
        }
        __syncthreads();

        // ---- PV: all 8 pages, packed f32x2 FMAs, p via broadcast LDS.128 ---
        uint64_t pvA[QPG], pvB[QPG];
        #pragma unroll
        for (int h = 0; h < QPG; h++) { pvA[h] = 0ull; pvB[h] = 0ull; }

        #pragma unroll 2
        for (int base = 0; base < CHUNK; base += 16) {
            const uint32_t po = ((uint32_t)bt_s[base >> 4]) << 16;
            const ulonglong2 va = *(const ulonglong2*)(vwp + po);
            const ulonglong2 vb = *(const ulonglong2*)(vwp + po + 4096);
            const int ra = (base + warp) * QPG;
            const float4 pA = *(const float4*)(logits + ra);
            const float4 pB = *(const float4*)(logits + ra + 8 * QPG);
            const float pAa[4] = {pA.x, pA.y, pA.z, pA.w};
            const float pBa[4] = {pB.x, pB.y, pB.z, pB.w};
            #pragma unroll
            for (int h = 0; h < QPG; h++) {
                const uint64_t ppa = pack2(pAa[h]);
                ffma2(pvA[h], va.x, ppa);
                ffma2(pvB[h], va.y, ppa);
                const uint64_t ppb = pack2(pBa[h]);
                ffma2(pvA[h], vb.x, ppb);
                ffma2(pvB[h], vb.y, ppb);
            }
        }

        // ---- cross-warp (8-way) reduction, write partials ------------------
        __syncthreads();
        float4* red = (float4*)smem;   // [8 warps][QPG][32 float4]
        #pragma unroll
        for (int h = 0; h < QPG; h++) {
            const float2 a = unpack2(pvA[h]);
            const float2 b = unpack2(pvB[h]);
            red[(warp * QPG + h) * 32 + lane] = make_float4(a.x, a.y, b.x, b.y);
        }
        __syncthreads();

        #pragma unroll
        for (int it = 0; it < 2; it++) {
            const int idx = tid + it * 256;     // (h, d)
            const int h = idx >> 7, d = idx & 127;
            float v = 0.0f;
            #pragma unroll
            for (int e = 0; e < 8; e++)
                v += smem[(e * QPG + h) * 128 + d];
            g_num[P][h][d] = v;
        }
        if (tid < QPG) { g_m[P][tid] = m_s[tid]; g_e[P][tid] = e_s[tid]; }
    } else {
        // Empty partial: merge weight is exactly 0; skip num writes.
        if (tid < QPG) { g_m[P][tid] = -1e30f; g_e[P][tid] = 0.0f; }
    }

    // ---- last-block arrival + fused reduce ---------------------------------
    __syncthreads();                 // all global writes of this CTA issued
    if (tid == 0) {
        __threadfence();             // release
        is_last_s = (atomicAdd(&g_cnt[sg], 1) == NPER - 1);
    }
    __syncthreads();
    if (!is_last_s) return;

    __threadfence();                 // acquire

    float* sm = smem;                // [NPER][QPG]
    float* se = smem + NPER * QPG;
    if (tid < NPER * QPG) {
        const int p = tid >> 2, h = tid & 3;
        const int Pq = pidx(p >> 2, s, g, p & 3);   // p = w*4 + c
        sm[tid] = g_m[Pq][h];
        se[p * QPG + h] = g_e[Pq][h];
    }
    __syncthreads();

    #pragma unroll
    for (int it = 0; it < 2; it++) {
        const int idx = tid + it * 256;     // (h, d)
        const int h = idx >> 7, d = idx & 127;
        float gmax = -1e30f;
        #pragma unroll
        for (int p = 0; p < NPER; p++)
            gmax = fmaxf(gmax, sm[p * QPG + h]);
        float den = 0.0f, val = 0.0f;
        #pragma unroll
        for (int p = 0; p < NPER; p++) {
            const float wgt = __expf(sm[p * QPG + h] - gmax);
            const int Pq = pidx(p >> 2, s, g, p & 3);
            den = fmaf(se[p * QPG + h], wgt, den);
            val = fmaf(g_num[Pq][h][d], wgt, val);
        }
        out[(size_t)sg * (QPG * HEAD_SIZE) + h * HEAD_SIZE + d] = val / den;
    }

    if (tid == 0) g_cnt[sg] = 0;
}

extern "C" void kernel_launch(void* const* d_in, const int* in_sizes, int n_in,
                              void* d_out, int out_size)
{
    const float* query        = (const float*)d_in[0];
    const float* key_cache    = (const float*)d_in[1];
    const float* value_cache  = (const float*)d_in[2];
    const int*   block_tables = (const int*)d_in[3];
    const int*   context_lens = (const int*)d_in[4];
    float*       out          = (float*)d_out;

    dim3 grid(NSEQ * GKV, WRANKS, NCHUNK);
    dpa_fused<<<grid, 256>>>(query, key_cache, value_cache,
                             block_tables, context_lens, out);
}

// round 9
// speedup vs baseline: 1.1849x; 1.1609x over previous
#include <cuda_runtime.h>
#include <stdint.h>
#include <math.h>

#define WRANKS 4
#define NUM_HEADS 32
#define HEAD_SIZE 128
#define GKV 8              // kv heads
#define QPG 4              // query heads per kv head
#define BLOCK_SIZE 16
#define NUM_BLOCKS 1024
#define MAX_BLOCKS 32
#define MAX_CTX 512
#define NSEQ 32
#define NCHUNK 4
#define CHUNK 128
#define NPER (WRANKS * NCHUNK)                 // 16 partials per (seq, g)
#define NPART (NSEQ * GKV * NPER)              // 4096 partials
#define ATT_SCALE 0.08838834764831845f         // 1/sqrt(128)

#define PAGE_BYTES 65536                       // GKV*BLOCK_SIZE*HEAD_SIZE*4
#define RANK_BYTES ((size_t)NUM_BLOCKS * PAGE_BYTES)
#define GOFF_BYTES (BLOCK_SIZE * HEAD_SIZE * 4)  // 8192

// Partial-result scratch — __device__ globals.
__device__ float g_num[NPART][QPG][HEAD_SIZE]; // 8 MB
__device__ float g_m[NPART][QPG];
__device__ float g_e[NPART][QPG];
__device__ int   g_cnt[NSEQ * GKV];            // arrival counters (reset by last CTA)

__device__ __forceinline__ int pidx(int w, int s, int g, int c) {
    return ((w * NSEQ + s) * GKV + g) * NCHUNK + c;
}

// Merge two butterfly-reduction streams (1 SHFL per merge).
__device__ __forceinline__ float mergestep(float x, float y, int cond, int d) {
    const float keep = cond ? y : x;
    const float send = cond ? x : y;
    return keep + __shfl_xor_sync(0xFFFFFFFFu, send, d);
}

__device__ __forceinline__ uint64_t pack2(float p) {
    const uint32_t u = __float_as_uint(p);
    uint64_t r;
    asm("mov.b64 %0, {%1, %2};" : "=l"(r) : "r"(u), "r"(u));
    return r;
}
__device__ __forceinline__ void ffma2(uint64_t& acc, uint64_t a, uint64_t b) {
    asm("fma.rn.f32x2 %0, %1, %2, %0;" : "+l"(acc) : "l"(a), "l"(b));
}
__device__ __forceinline__ float2 unpack2(uint64_t v) {
    uint32_t lo, hi;
    asm("mov.b64 {%0, %1}, %2;" : "=r"(lo), "=r"(hi) : "l"(v));
    return make_float2(__uint_as_float(lo), __uint_as_float(hi));
}

// ---------------------------------------------------------------------------
// Fused kernel: partial attention + last-block cross-partial LSE merge.
// grid = (NSEQ*GKV, WRANKS, NCHUNK), block = 256
// ---------------------------------------------------------------------------
__global__ __launch_bounds__(256, 5)
void dpa_fused(const float* __restrict__ query,
               const float* __restrict__ key_cache,
               const float* __restrict__ value_cache,
               const int*   __restrict__ block_tables,
               const int*   __restrict__ context_lens,
               float*       __restrict__ out)
{
    __shared__ float smem[5120];          // 20 KB: logits[512] + qs[512] + red[4096]
    __shared__ int   bt_s[8];             // this chunk's pages
    __shared__ float m_s[QPG], e_s[QPG];
    __shared__ int   is_last_s;

    const int sg   = blockIdx.x;          // 0..255
    const int s    = sg >> 3;
    const int g    = sg & 7;
    const int w    = blockIdx.y;
    const int c    = blockIdx.z;
    const int tid  = threadIdx.x;
    const int lane = tid & 31;
    const int warp = tid >> 5;

    const int P   = pidx(w, s, g, c);
    const int ctx = context_lens[w * NSEQ + s];
    const int t0  = c * CHUNK;
    const int n   = min(ctx - t0, CHUNK);   // may be <=0

    if (n > 0) {
        const int npages = (n + 15) >> 4;    // 1..8 live pages in this chunk

        if (tid < 8)
            bt_s[tid] = block_tables[((size_t)w * NSEQ + s) * MAX_BLOCKS + c * 8 + tid];

        float* logits = smem;         // [CHUNK][QPG] transposed
        float* qs     = smem + 512;   // [QPG][HEAD_SIZE], pre-scaled
        float* red    = smem + 1024;  // [8][QPG][HEAD_SIZE]

        for (int i = tid; i < QPG * HEAD_SIZE; i += 256)
            qs[i] = query[(size_t)s * (NUM_HEADS * HEAD_SIZE)
                          + (size_t)g * (QPG * HEAD_SIZE) + i] * ATT_SCALE;
        __syncthreads();

        const char* kwp = (const char*)key_cache + (size_t)w * RANK_BYTES
                        + g * GOFF_BYTES + warp * 512 + lane * 16;
        const char* vwp = (const char*)value_cache + (size_t)w * RANK_BYTES
                        + g * GOFF_BYTES + warp * 512 + lane * 16;
        const float* qlp = qs + lane * 4;
        const int cb0 = lane & 1, cb1 = lane & 2, cb2 = lane & 4;

        // ---- QK: live pages only, guard-free 16-token body -----------------
        #pragma unroll 2
        for (int pg = 0; pg < npages; pg++) {
            const uint32_t po = ((uint32_t)bt_s[pg]) << 16;
            const float4 ka = *(const float4*)(kwp + po);
            const float4 kb = *(const float4*)(kwp + po + 4096);
            float pa[QPG], pb[QPG];
            #pragma unroll
            for (int h = 0; h < QPG; h++) {
                const float4 q4 = *(const float4*)(qlp + h * HEAD_SIZE);
                float x = ka.x * q4.x;
                x = fmaf(ka.y, q4.y, x);
                x = fmaf(ka.z, q4.z, x);
                x = fmaf(ka.w, q4.w, x);
                pa[h] = x;
                float y = kb.x * q4.x;
                y = fmaf(kb.y, q4.y, y);
                y = fmaf(kb.z, q4.z, y);
                y = fmaf(kb.w, q4.w, y);
                pb[h] = y;
            }
            const float r01 = mergestep(pa[0], pa[1], cb0, 1);
            const float r23 = mergestep(pa[2], pa[3], cb0, 1);
            const float s01 = mergestep(pb[0], pb[1], cb0, 1);
            const float s23 = mergestep(pb[2], pb[3], cb0, 1);
            const float r   = mergestep(r01, r23, cb1, 2);
            const float sB  = mergestep(s01, s23, cb1, 2);
            float t = mergestep(r, sB, cb2, 4);
            t += __shfl_xor_sync(0xFFFFFFFFu, t, 8);
            t += __shfl_xor_sync(0xFFFFFFFFu, t, 16);
            if (lane < 8) {
                const int tok = pg * 16 + warp + ((lane >> 2) << 3);
                logits[tok * QPG + (lane & 3)] = t;
            }
        }
        __syncthreads();

        // ---- softmax (warps 0-3), tail zero-fill (warps 4-7) ---------------
        if (warp < QPG) {
            const int h = warp;
            float mx = -1e30f;
            for (int t = lane; t < n; t += 32)
                mx = fmaxf(mx, logits[t * QPG + h]);
            #pragma unroll
            for (int off = 16; off; off >>= 1)
                mx = fmaxf(mx, __shfl_xor_sync(0xFFFFFFFFu, mx, off));
            float sum = 0.0f;
            for (int t = lane; t < n; t += 32) {
                const float p = __expf(logits[t * QPG + h] - mx);
                logits[t * QPG + h] = p;
                sum += p;
            }
            #pragma unroll
            for (int off = 16; off; off >>= 1)
                sum += __shfl_xor_sync(0xFFFFFFFFu, sum, off);
            if (lane == 0) { m_s[h] = mx; e_s[h] = sum; }
        } else {
            for (int i = n * QPG + (tid - 128); i < npages * 16 * QPG; i += 128)
                logits[i] = 0.0f;
        }
        __syncthreads();

        // ---- PV: live pages, packed f32x2 FMAs, p via broadcast LDS.128 ----
        uint64_t pvA[QPG], pvB[QPG];
        #pragma unroll
        for (int h = 0; h < QPG; h++) { pvA[h] = 0ull; pvB[h] = 0ull; }

        #pragma unroll 2
        for (int pg = 0; pg < npages; pg++) {
            const uint32_t po = ((uint32_t)bt_s[pg]) << 16;
            const ulonglong2 va = *(const ulonglong2*)(vwp + po);
            const ulonglong2 vb = *(const ulonglong2*)(vwp + po + 4096);
            const int ra = (pg * 16 + warp) * QPG;
            const float4 pA = *(const float4*)(logits + ra);
            const float4 pB = *(const float4*)(logits + ra + 8 * QPG);
            const float pAa[4] = {pA.x, pA.y, pA.z, pA.w};
            const float pBa[4] = {pB.x, pB.y, pB.z, pB.w};
            #pragma unroll
            for (int h = 0; h < QPG; h++) {
                const uint64_t ppa = pack2(pAa[h]);
                ffma2(pvA[h], va.x, ppa);
                ffma2(pvB[h], va.y, ppa);
                const uint64_t ppb = pack2(pBa[h]);
                ffma2(pvA[h], vb.x, ppb);
                ffma2(pvB[h], vb.y, ppb);
            }
        }

        // ---- cross-warp (8-way) reduction, write partials ------------------
        // red is disjoint from logits — no barrier needed before the store.
        float4* red4 = (float4*)red;   // [8 warps][QPG][32 float4]
        #pragma unroll
        for (int h = 0; h < QPG; h++) {
            const float2 a = unpack2(pvA[h]);
            const float2 b = unpack2(pvB[h]);
            red4[(warp * QPG + h) * 32 + lane] = make_float4(a.x, a.y, b.x, b.y);
        }
        __syncthreads();

        #pragma unroll
        for (int it = 0; it < 2; it++) {
            const int idx = tid + it * 256;     // (h, d)
            const int h = idx >> 7, d = idx & 127;
            float v = 0.0f;
            #pragma unroll
            for (int e = 0; e < 8; e++)
                v += red[(e * QPG + h) * 128 + d];
            g_num[P][h][d] = v;
        }
        if (tid < QPG) { g_m[P][tid] = m_s[tid]; g_e[P][tid] = e_s[tid]; }
    } else {
        // Empty partial: merge weight is exactly 0; skip num writes.
        if (tid < QPG) { g_m[P][tid] = -1e30f; g_e[P][tid] = 0.0f; }
    }

    // ---- last-block arrival + fused reduce ---------------------------------
    __syncthreads();                 // all global writes of this CTA issued
    if (tid == 0) {
        __threadfence();             // release
        is_last_s = (atomicAdd(&g_cnt[sg], 1) == NPER - 1);
    }
    __syncthreads();
    if (!is_last_s) return;

    __threadfence();                 // acquire

    float* sm = smem;                // [NPER][QPG]
    float* se = smem + NPER * QPG;
    if (tid < NPER * QPG) {
        const int p = tid >> 2, h = tid & 3;
        const int Pq = pidx(p >> 2, s, g, p & 3);   // p = w*4 + c
        sm[tid] = g_m[Pq][h];
        se[p * QPG + h] = g_e[Pq][h];
    }
    __syncthreads();

    #pragma unroll
    for (int it = 0; it < 2; it++) {
        const int idx = tid + it * 256;     // (h, d)
        const int h = idx >> 7, d = idx & 127;
        float gmax = -1e30f;
        #pragma unroll
        for (int p = 0; p < NPER; p++)
            gmax = fmaxf(gmax, sm[p * QPG + h]);
        float den = 0.0f, val = 0.0f;
        #pragma unroll
        for (int p = 0; p < NPER; p++) {
            const float wgt = __expf(sm[p * QPG + h] - gmax);
            const int Pq = pidx(p >> 2, s, g, p & 3);
            den = fmaf(se[p * QPG + h], wgt, den);
            val = fmaf(g_num[Pq][h][d], wgt, val);
        }
        out[(size_t)sg * (QPG * HEAD_SIZE) + h * HEAD_SIZE + d] = val / den;
    }

    if (tid == 0) g_cnt[sg] = 0;
}

extern "C" void kernel_launch(void* const* d_in, const int* in_sizes, int n_in,
                              void* d_out, int out_size)
{
    const float* query        = (const float*)d_in[0];
    const float* key_cache    = (const float*)d_in[1];
    const float* value_cache  = (const float*)d_in[2];
    const int*   block_tables = (const int*)d_in[3];
    const int*   context_lens = (const int*)d_in[4];
    float*       out          = (float*)d_out;

    dim3 grid(NSEQ * GKV, WRANKS, NCHUNK);
    dpa_fused<<<grid, 256>>>(query, key_cache, value_cache,
                             block_tables, context_lens, out);
}

// round 10
// speedup vs baseline: 1.3103x; 1.1059x over previous
#include <cuda_runtime.h>
#include <stdint.h>
#include <math.h>

#define WRANKS 4
#define NUM_HEADS 32
#define HEAD_SIZE 128
#define GKV 8              // kv heads
#define QPG 4              // query heads per kv head
#define BLOCK_SIZE 16
#define NUM_BLOCKS 1024
#define MAX_BLOCKS 32
#define MAX_CTX 512
#define NSEQ 32
#define NCHUNK 4
#define CHUNK 128
#define NPER (WRANKS * NCHUNK)                 // 16 partials per (seq, g)
#define NPART (NSEQ * GKV * NPER)              // 4096 partials
#define ATT_SCALE 0.08838834764831845f         // 1/sqrt(128)

#define PAGE_BYTES 65536                       // GKV*BLOCK_SIZE*HEAD_SIZE*4
#define RANK_BYTES ((size_t)NUM_BLOCKS * PAGE_BYTES)
#define GOFF_BYTES (BLOCK_SIZE * HEAD_SIZE * 4)  // 8192

// Partial-result scratch — __device__ globals.
__device__ float g_num[NPART][QPG][HEAD_SIZE]; // 8 MB
__device__ float g_m[NPART][QPG];
__device__ float g_e[NPART][QPG];
__device__ int   g_cnt[NSEQ * GKV];            // arrival counters (reset by last CTA)

__device__ __forceinline__ int pidx(int w, int s, int g, int c) {
    return ((w * NSEQ + s) * GKV + g) * NCHUNK + c;
}

// Merge two butterfly-reduction streams (1 SHFL per merge).
__device__ __forceinline__ float mergestep(float x, float y, int cond, int d) {
    const float keep = cond ? y : x;
    const float send = cond ? x : y;
    return keep + __shfl_xor_sync(0xFFFFFFFFu, send, d);
}

__device__ __forceinline__ uint64_t pack2(float p) {
    const uint32_t u = __float_as_uint(p);
    uint64_t r;
    asm("mov.b64 %0, {%1, %2};" : "=l"(r) : "r"(u), "r"(u));
    return r;
}
__device__ __forceinline__ void ffma2(uint64_t& acc, uint64_t a, uint64_t b) {
    asm("fma.rn.f32x2 %0, %1, %2, %0;" : "+l"(acc) : "l"(a), "l"(b));
}
__device__ __forceinline__ float2 unpack2(uint64_t v) {
    uint32_t lo, hi;
    asm("mov.b64 {%0, %1}, %2;" : "=r"(lo), "=r"(hi) : "l"(v));
    return make_float2(__uint_as_float(lo), __uint_as_float(hi));
}

// ---------------------------------------------------------------------------
// Fused kernel: partial attention + last-block cross-partial LSE merge.
// grid = (NSEQ*GKV, WRANKS, NCHUNK), block = 128 (4 warps)
// ---------------------------------------------------------------------------
__global__ __launch_bounds__(128, 10)
void dpa_fused(const float* __restrict__ query,
               const float* __restrict__ key_cache,
               const float* __restrict__ value_cache,
               const int*   __restrict__ block_tables,
               const int*   __restrict__ context_lens,
               float*       __restrict__ out)
{
    __shared__ float smem[3072];          // 12 KB: logits[512] + qs[512] + red[2048]
    __shared__ int   bt_s[8];             // this chunk's pages
    __shared__ float m_s[QPG], e_s[QPG];
    __shared__ int   is_last_s;

    const int sg   = blockIdx.x;          // 0..255
    const int s    = sg >> 3;
    const int g    = sg & 7;
    const int w    = blockIdx.y;
    const int c    = blockIdx.z;
    const int tid  = threadIdx.x;
    const int lane = tid & 31;
    const int warp = tid >> 5;            // 0..3

    const int P   = pidx(w, s, g, c);
    const int ctx = context_lens[w * NSEQ + s];
    const int t0  = c * CHUNK;
    const int n   = min(ctx - t0, CHUNK);   // may be <=0

    if (n > 0) {
        const int npages = (n + 15) >> 4;    // 1..8 live pages in this chunk

        if (tid < 8)
            bt_s[tid] = block_tables[((size_t)w * NSEQ + s) * MAX_BLOCKS + c * 8 + tid];

        float* logits = smem;         // [CHUNK][QPG] transposed
        float* qs     = smem + 512;   // [QPG][HEAD_SIZE], pre-scaled
        float* red    = smem + 1024;  // [4 warps][QPG][HEAD_SIZE]

        for (int i = tid; i < QPG * HEAD_SIZE; i += 128)
            qs[i] = query[(size_t)s * (NUM_HEADS * HEAD_SIZE)
                          + (size_t)g * (QPG * HEAD_SIZE) + i] * ATT_SCALE;
        __syncthreads();

        // warp covers tokens {warp, warp+4, warp+8, warp+12} of each page
        const char* kwp = (const char*)key_cache + (size_t)w * RANK_BYTES
                        + g * GOFF_BYTES + warp * 512 + lane * 16;
        const char* vwp = (const char*)value_cache + (size_t)w * RANK_BYTES
                        + g * GOFF_BYTES + warp * 512 + lane * 16;
        const float* qlp = qs + lane * 4;
        const int cb0 = lane & 1, cb1 = lane & 2, cb2 = lane & 4, cb3 = lane & 8;

        // ---- QK: live pages only, 4 tokens in flight per warp --------------
        #pragma unroll 2
        for (int pg = 0; pg < npages; pg++) {
            const uint32_t po = ((uint32_t)bt_s[pg]) << 16;
            float4 k4[4];
            #pragma unroll
            for (int j = 0; j < 4; j++)
                k4[j] = *(const float4*)(kwp + po + j * 2048);   // token warp+4j

            float p[4][QPG];
            #pragma unroll
            for (int j = 0; j < 4; j++) {
                #pragma unroll
                for (int h = 0; h < QPG; h++) {
                    const float4 q4 = *(const float4*)(qlp + h * HEAD_SIZE);
                    float x = k4[j].x * q4.x;
                    x = fmaf(k4[j].y, q4.y, x);
                    x = fmaf(k4[j].z, q4.z, x);
                    x = fmaf(k4[j].w, q4.w, x);
                    p[j][h] = x;
                }
            }
            // merged reduction of 16 series: head = lane bits 0-1, token = bits 2-3
            float mh[4];
            #pragma unroll
            for (int j = 0; j < 4; j++) {
                const float a = mergestep(p[j][0], p[j][1], cb0, 1);
                const float b = mergestep(p[j][2], p[j][3], cb0, 1);
                mh[j] = mergestep(a, b, cb1, 2);
            }
            const float t01 = mergestep(mh[0], mh[1], cb2, 4);
            const float t23 = mergestep(mh[2], mh[3], cb2, 4);
            float t = mergestep(t01, t23, cb3, 8);
            t += __shfl_xor_sync(0xFFFFFFFFu, t, 16);
            if (lane < 16) {
                const int tok = pg * 16 + warp + ((lane >> 2) << 2);
                logits[tok * QPG + (lane & 3)] = t;
            }
        }
        __syncthreads();

        // ---- softmax (one warp per head), tail zero-fill folded in ---------
        {
            const int h = warp;
            float mx = -1e30f;
            for (int t = lane; t < n; t += 32)
                mx = fmaxf(mx, logits[t * QPG + h]);
            #pragma unroll
            for (int off = 16; off; off >>= 1)
                mx = fmaxf(mx, __shfl_xor_sync(0xFFFFFFFFu, mx, off));
            float sum = 0.0f;
            for (int t = lane; t < n; t += 32) {
                const float p = __expf(logits[t * QPG + h] - mx);
                logits[t * QPG + h] = p;
                sum += p;
            }
            #pragma unroll
            for (int off = 16; off; off >>= 1)
                sum += __shfl_xor_sync(0xFFFFFFFFu, sum, off);
            if (lane == 0) { m_s[h] = mx; e_s[h] = sum; }
            // zero the tail of this head's column (garbage logits of last page)
            for (int t = n + lane; t < npages * 16; t += 32)
                logits[t * QPG + h] = 0.0f;
        }
        __syncthreads();

        // ---- PV: 4 independent V LDG.128 per page, packed f32x2 FMAs -------
        uint64_t pvA[QPG], pvB[QPG];
        #pragma unroll
        for (int h = 0; h < QPG; h++) { pvA[h] = 0ull; pvB[h] = 0ull; }

        #pragma unroll 2
        for (int pg = 0; pg < npages; pg++) {
            const uint32_t po = ((uint32_t)bt_s[pg]) << 16;
            ulonglong2 v4[4];
            #pragma unroll
            for (int j = 0; j < 4; j++)
                v4[j] = *(const ulonglong2*)(vwp + po + j * 2048);
            #pragma unroll
            for (int j = 0; j < 4; j++) {
                const float4 pj = *(const float4*)(logits + (pg * 16 + warp + 4 * j) * QPG);
                const float pja[4] = {pj.x, pj.y, pj.z, pj.w};
                #pragma unroll
                for (int h = 0; h < QPG; h++) {
                    const uint64_t pp = pack2(pja[h]);
                    ffma2(pvA[h], v4[j].x, pp);
                    ffma2(pvB[h], v4[j].y, pp);
                }
            }
        }

        // ---- cross-warp (4-way) reduction, write partials ------------------
        float4* red4 = (float4*)red;   // [4 warps][QPG][32 float4]
        #pragma unroll
        for (int h = 0; h < QPG; h++) {
            const float2 a = unpack2(pvA[h]);
            const float2 b = unpack2(pvB[h]);
            red4[(warp * QPG + h) * 32 + lane] = make_float4(a.x, a.y, b.x, b.y);
        }
        __syncthreads();

        #pragma unroll
        for (int it = 0; it < 4; it++) {
            const int idx = tid + it * 128;     // (h, d)
            const int h = idx >> 7, d = idx & 127;
            float v = 0.0f;
            #pragma unroll
            for (int e = 0; e < 4; e++)
                v += red[(e * QPG + h) * 128 + d];
            g_num[P][h][d] = v;
        }
        if (tid < QPG) { g_m[P][tid] = m_s[tid]; g_e[P][tid] = e_s[tid]; }
    } else {
        // Empty partial: merge weight is exactly 0; skip num writes.
        if (tid < QPG) { g_m[P][tid] = -1e30f; g_e[P][tid] = 0.0f; }
    }

    // ---- last-block arrival + fused reduce ---------------------------------
    __syncthreads();                 // all global writes of this CTA issued
    if (tid == 0) {
        __threadfence();             // release
        is_last_s = (atomicAdd(&g_cnt[sg], 1) == NPER - 1);
    }
    __syncthreads();
    if (!is_last_s) return;

    __threadfence();                 // acquire

    float* sm = smem;                // [NPER][QPG]
    float* se = smem + NPER * QPG;
    if (tid < NPER * QPG) {
        const int p = tid >> 2, h = tid & 3;
        const int Pq = pidx(p >> 2, s, g, p & 3);   // p = w*4 + c
        sm[tid] = g_m[Pq][h];
        se[p * QPG + h] = g_e[Pq][h];
    }
    __syncthreads();

    #pragma unroll
    for (int it = 0; it < 4; it++) {
        const int idx = tid + it * 128;     // (h, d)
        const int h = idx >> 7, d = idx & 127;
        float gmax = -1e30f;
        #pragma unroll
        for (int p = 0; p < NPER; p++)
            gmax = fmaxf(gmax, sm[p * QPG + h]);
        float den = 0.0f, val = 0.0f;
        #pragma unroll
        for (int p = 0; p < NPER; p++) {
            const float wgt = __expf(sm[p * QPG + h] - gmax);
            const int Pq = pidx(p >> 2, s, g, p & 3);
            den = fmaf(se[p * QPG + h], wgt, den);
            val = fmaf(g_num[Pq][h][d], wgt, val);
        }
        out[(size_t)sg * (QPG * HEAD_SIZE) + h * HEAD_SIZE + d] = val / den;
    }

    if (tid == 0) g_cnt[sg] = 0;
}

extern "C" void kernel_launch(void* const* d_in, const int* in_sizes, int n_in,
                              void* d_out, int out_size)
{
    const float* query        = (const float*)d_in[0];
    const float* key_cache    = (const float*)d_in[1];
    const float* value_cache  = (const float*)d_in[2];
    const int*   block_tables = (const int*)d_in[3];
    const int*   context_lens = (const int*)d_in[4];
    float*       out          = (float*)d_out;

    dim3 grid(NSEQ * GKV, WRANKS, NCHUNK);
    dpa_fused<<<grid, 128>>>(query, key_cache, value_cache,
                             block_tables, context_lens, out);
}